// round 1
// baseline (speedup 1.0000x reference)
#include <cuda_runtime.h>
#include <cstdint>

// ---------------------------------------------------------------------------
// ASE block: B=16, DIM=256, H=W=64, KEY_DIM=16, HEADS=8, NH_KD=128, DH=256
// N = B*H*W = 65536 spatial positions. All fp32.
//
// Pipeline:
//  1. prep      : fold BN scales into weight matrices
//  2. gemm<0>   : qkv0[512][N] = Wall @ x + ball          (q,k,v channels)
//  3. mean      : row/col means of qkv0 per (c,b)
//  4. attn      : axial attention (row + col), 16-len softmax seqs of 64
//  5. proj      : relu + Wr/Wc projection of attention outputs
//  6. gemm<1>   : qkvg[256][N] = Wpw2 @ relu(qkv0*gs+gb) + bpw   (gating)
//  7. gemm<2>   : out = hsig(Wp2 @ relu(v+xr+xc) + bp) * qkvg
// ---------------------------------------------------------------------------

#define NB    16
#define CDIM  256
#define HH    64
#define WW    64
#define HWSZ  4096
#define NTOT  65536
#define MQKV  512
#define DHV   256

// ---- device scratch (no allocations allowed) ----
__device__ float g_Wall[512 * 256];
__device__ float g_ball[512];
__device__ float g_gs[512];
__device__ float g_gb[512];
__device__ float g_Wpw2[256 * 512];
__device__ float g_Wr2[256 * 256];
__device__ float g_Wc2[256 * 256];
__device__ float g_Wp2[256 * 256];
__device__ float g_qkv0[(size_t)512 * 65536];   // 128 MB
__device__ float g_qkvg[(size_t)256 * 65536];   //  64 MB
__device__ float g_rmean[512 * 16 * 64];
__device__ float g_cmean[512 * 16 * 64];
__device__ float g_attnpre[2 * 16 * 256 * 64];
__device__ float g_attnout[2 * 16 * 256 * 64];

// ---------------------------------------------------------------------------
// 1. weight prep: fold BN scale into weights
// ---------------------------------------------------------------------------
__global__ void prep_kernel(
    const float* __restrict__ Wq, const float* __restrict__ sq, const float* __restrict__ bq,
    const float* __restrict__ Wk, const float* __restrict__ sk, const float* __restrict__ bk,
    const float* __restrict__ Wv, const float* __restrict__ sv, const float* __restrict__ bv,
    const float* __restrict__ wdw, const float* __restrict__ sdw, const float* __restrict__ bdw,
    const float* __restrict__ Wpw, const float* __restrict__ spw,
    const float* __restrict__ Wr,  const float* __restrict__ sr,
    const float* __restrict__ Wc,  const float* __restrict__ sc,
    const float* __restrict__ Wp,  const float* __restrict__ sp)
{
    int i = blockIdx.x * 256 + threadIdx.x;     // 131072 threads total
    // Wall (512 x 256): rows 0-127 q, 128-255 k, 256-511 v
    {
        int m = i >> 8, c = i & 255;
        float w, s;
        if (m < 128)      { w = Wq[m * 256 + c];         s = sq[m]; }
        else if (m < 256) { w = Wk[(m - 128) * 256 + c]; s = sk[m - 128]; }
        else              { w = Wv[(m - 256) * 256 + c]; s = sv[m - 256]; }
        g_Wall[i] = w * s;
    }
    // Wpw2 (256 x 512)
    {
        int m = i >> 9;
        g_Wpw2[i] = Wpw[i] * spw[m];
    }
    if (i < 65536) {
        int m = i >> 8;
        g_Wr2[i] = Wr[i] * sr[m];
        g_Wc2[i] = Wc[i] * sc[m];
        g_Wp2[i] = Wp[i] * sp[m];
    }
    if (i < 512) {
        g_gs[i] = wdw[i] * sdw[i];
        g_gb[i] = bdw[i];
        float b;
        if (i < 128)      b = bq[i];
        else if (i < 256) b = bk[i - 128];
        else              b = bv[i - 256];
        g_ball[i] = b;
    }
}

// ---------------------------------------------------------------------------
// Tiled GEMM: BM=64, BN=128, BK=16, 256 threads, 4x8 per thread.
// MODE 0: qkv = Wall @ x            -> g_qkv0
// MODE 1: qkvg = Wpw2 @ relu(gate)  -> g_qkvg
// MODE 2: out = hsig(Wp2 @ relu(v+xr+xc) + bp) * qkvg -> d_out
// ---------------------------------------------------------------------------
template <int MODE>
__global__ void __launch_bounds__(256) gemm_kernel(
    const float* __restrict__ xin,     // MODE 0 input x
    const float* __restrict__ biasM,   // MODE 1: bpw, MODE 2: bp (MODE 0 uses g_ball)
    float* __restrict__ outp,          // MODE 2: d_out
    int K)
{
    __shared__ float As[16][68];
    __shared__ float Bs[16][132];
    const int tid = threadIdx.x;
    const int bm  = blockIdx.y * 64;
    const int bn0 = blockIdx.x * 128;
    const int tx  = tid & 15;
    const int ty  = tid >> 4;

    const float* __restrict__ Aw =
        (MODE == 0) ? g_Wall : ((MODE == 1) ? g_Wpw2 : g_Wp2);

    float acc[4][8];
    #pragma unroll
    for (int i = 0; i < 4; i++)
        #pragma unroll
        for (int j = 0; j < 8; j++) acc[i][j] = 0.0f;

    for (int k0 = 0; k0 < K; k0 += 16) {
        // A tile: 64 rows x 16 k
        #pragma unroll
        for (int l = 0; l < 4; l++) {
            int idx = tid + l * 256;
            int m = idx >> 4, kk = idx & 15;
            As[kk][m] = Aw[(size_t)(bm + m) * K + k0 + kk];
        }
        // B tile: 16 k x 128 n (with fused pre-ops)
        #pragma unroll
        for (int l = 0; l < 8; l++) {
            int idx = tid + l * 256;
            int kk = idx >> 7;
            int nl = idx & 127;
            int n  = bn0 + nl;
            int k  = k0 + kk;
            float v;
            if (MODE == 0) {
                int b = n >> 12, hw = n & 4095;
                v = xin[(size_t)b * 1048576 + (size_t)k * 4096 + hw];
            } else if (MODE == 1) {
                float t = g_qkv0[(size_t)k * 65536 + n];
                v = fmaxf(t * g_gs[k] + g_gb[k], 0.0f);
            } else {
                int b = n >> 12, hw = n & 4095, h = hw >> 6, w = hw & 63;
                float t = g_qkv0[(size_t)(256 + k) * 65536 + n]
                        + g_attnout[(size_t)(b * 256 + k) * 64 + h]
                        + g_attnout[(size_t)((16 + b) * 256 + k) * 64 + w];
                v = fmaxf(t, 0.0f);
            }
            Bs[kk][nl] = v;
        }
        __syncthreads();
        #pragma unroll
        for (int kk = 0; kk < 16; kk++) {
            float4 a4 = *(const float4*)&As[kk][ty * 4];
            float4 b0 = *(const float4*)&Bs[kk][tx * 8];
            float4 b1 = *(const float4*)&Bs[kk][tx * 8 + 4];
            float a[4] = {a4.x, a4.y, a4.z, a4.w};
            float b[8] = {b0.x, b0.y, b0.z, b0.w, b1.x, b1.y, b1.z, b1.w};
            #pragma unroll
            for (int i = 0; i < 4; i++)
                #pragma unroll
                for (int j = 0; j < 8; j++)
                    acc[i][j] += a[i] * b[j];
        }
        __syncthreads();
    }

    // epilogue
    #pragma unroll
    for (int i = 0; i < 4; i++) {
        int m = bm + ty * 4 + i;
        float bias = (MODE == 0) ? g_ball[m] : biasM[m];
        int n0 = bn0 + tx * 8;
        #pragma unroll
        for (int j = 0; j < 8; j++) {
            int n = n0 + j;
            float y = acc[i][j] + bias;
            if (MODE == 0) {
                g_qkv0[(size_t)m * 65536 + n] = y;
            } else if (MODE == 1) {
                g_qkvg[(size_t)m * 65536 + n] = y;
            } else {
                int b = n >> 12, hw = n & 4095;
                float hs = fminf(fmaxf(y + 3.0f, 0.0f), 6.0f) * (1.0f / 6.0f);
                outp[(size_t)b * 1048576 + (size_t)m * 4096 + hw] =
                    hs * g_qkvg[(size_t)m * 65536 + n];
            }
        }
    }
}

// ---------------------------------------------------------------------------
// 3. row/col means: one block per (channel c, batch b)
// ---------------------------------------------------------------------------
__global__ void mean_kernel()
{
    __shared__ float sm[64][65];
    int bx = blockIdx.x;              // 8192 = 512 * 16
    int c = bx >> 4, b = bx & 15;
    const float* __restrict__ src = &g_qkv0[(size_t)c * 65536 + (size_t)b * 4096];
    int tid = threadIdx.x;            // 256
    for (int idx = tid; idx < 4096; idx += 256)
        sm[idx >> 6][idx & 63] = src[idx];
    __syncthreads();
    if (tid < 64) {
        float s = 0.0f;
        #pragma unroll
        for (int w = 0; w < 64; w++) s += sm[tid][w];
        g_rmean[(size_t)c * 1024 + b * 64 + tid] = s * (1.0f / 64.0f);
    } else if (tid < 128) {
        int w = tid - 64;
        float s = 0.0f;
        #pragma unroll
        for (int h = 0; h < 64; h++) s += sm[h][w];
        g_cmean[(size_t)c * 1024 + b * 64 + w] = s * (1.0f / 64.0f);
    }
}

// ---------------------------------------------------------------------------
// 4. axial attention: one block per (rc, b, head); 64 threads = seq positions
// ---------------------------------------------------------------------------
__global__ void attn_kernel(
    const float* __restrict__ pe_rq, const float* __restrict__ pe_rk,
    const float* __restrict__ pe_cq, const float* __restrict__ pe_ck)
{
    __shared__ float sQ[64][17];
    __shared__ float sK[64][17];
    __shared__ float sV[64][33];
    __shared__ float sS[64][65];
    int bx = blockIdx.x;              // 256 = 2 * 16 * 8
    int rc   = bx >> 7;
    int b    = (bx >> 3) & 15;
    int head = bx & 7;
    int i = threadIdx.x;              // 64 threads

    const float* __restrict__ mean = rc ? g_cmean : g_rmean;
    const float* __restrict__ peq  = rc ? pe_cq : pe_rq;
    const float* __restrict__ pek  = rc ? pe_ck : pe_rk;

    // linear-interp positional embedding at position i (S=16 -> N=64)
    float pos = fminf(fmaxf(0.25f * (float)i - 0.25f, 0.0f), 15.0f);
    int   i0  = (int)pos;
    int   i1  = min(i0 + 1, 15);
    float fw  = pos - (float)i0;

    #pragma unroll
    for (int kd = 0; kd < 16; kd++) {
        int cq = head * 16 + kd;           // q channel (0..127)
        float pq = peq[cq * 16 + i0] * (1.0f - fw) + peq[cq * 16 + i1] * fw;
        float pk = pek[cq * 16 + i0] * (1.0f - fw) + pek[cq * 16 + i1] * fw;
        sQ[i][kd] = mean[(size_t)cq * 1024 + b * 64 + i] + pq;
        sK[i][kd] = mean[(size_t)(128 + cq) * 1024 + b * 64 + i] + pk;
    }
    #pragma unroll
    for (int d = 0; d < 32; d++) {
        int cv = 256 + head * 32 + d;
        sV[i][d] = mean[(size_t)cv * 1024 + b * 64 + i];
    }
    __syncthreads();

    float mx = -1e30f;
    for (int j = 0; j < 64; j++) {
        float s = 0.0f;
        #pragma unroll
        for (int kd = 0; kd < 16; kd++) s += sQ[i][kd] * sK[j][kd];
        s *= 0.25f;                       // KEY_DIM^-0.5
        sS[i][j] = s;
        mx = fmaxf(mx, s);
    }
    float sum = 0.0f;
    for (int j = 0; j < 64; j++) {
        float e = expf(sS[i][j] - mx);
        sS[i][j] = e;
        sum += e;
    }
    float inv = 1.0f / sum;
    #pragma unroll 4
    for (int d = 0; d < 32; d++) {
        float o = 0.0f;
        for (int j = 0; j < 64; j++) o += sS[i][j] * sV[j][d];
        g_attnpre[(size_t)((rc * 16 + b) * 256 + head * 32 + d) * 64 + i] = o * inv;
    }
}

// ---------------------------------------------------------------------------
// 5. relu + Wr/Wc projection: (256 out ch x 64 pos) per (rc, b)
// ---------------------------------------------------------------------------
__global__ void proj_kernel(const float* __restrict__ br, const float* __restrict__ bc)
{
    int bx = blockIdx.x;              // 2048 = 2 * 16 * 64
    int rc = bx & 1;
    int b  = (bx >> 1) & 15;
    int ob = bx >> 5;                 // 0..63 -> 4 output channels each
    int tid = threadIdx.x;            // 256
    int h = tid & 63;
    int o = ob * 4 + (tid >> 6);

    const float* __restrict__ W    = rc ? g_Wc2 : g_Wr2;
    const float* __restrict__ bias = rc ? bc : br;
    const float* __restrict__ in   = &g_attnpre[(size_t)(rc * 16 + b) * 256 * 64];

    float acc = bias[o];
    #pragma unroll 8
    for (int k = 0; k < 256; k++)
        acc += W[o * 256 + k] * fmaxf(in[k * 64 + h], 0.0f);

    g_attnout[(size_t)((rc * 16 + b) * 256 + o) * 64 + h] = acc;
}

// ---------------------------------------------------------------------------
extern "C" void kernel_launch(void* const* d_in, const int* in_sizes, int n_in,
                              void* d_out, int out_size)
{
    (void)in_sizes; (void)n_in; (void)out_size;
    const float* x     = (const float*)d_in[0];
    const float* Wq    = (const float*)d_in[1];
    const float* sq    = (const float*)d_in[2];
    const float* bq    = (const float*)d_in[3];
    const float* Wk    = (const float*)d_in[4];
    const float* sk    = (const float*)d_in[5];
    const float* bk    = (const float*)d_in[6];
    const float* Wv    = (const float*)d_in[7];
    const float* sv    = (const float*)d_in[8];
    const float* bv    = (const float*)d_in[9];
    const float* pe_rq = (const float*)d_in[10];
    const float* pe_rk = (const float*)d_in[11];
    const float* pe_cq = (const float*)d_in[12];
    const float* pe_ck = (const float*)d_in[13];
    const float* wdw   = (const float*)d_in[14];
    const float* sdw   = (const float*)d_in[15];
    const float* bdw   = (const float*)d_in[16];
    const float* Wpw   = (const float*)d_in[17];
    const float* spw   = (const float*)d_in[18];
    const float* bpw   = (const float*)d_in[19];
    const float* Wr    = (const float*)d_in[20];
    const float* sr    = (const float*)d_in[21];
    const float* br    = (const float*)d_in[22];
    const float* Wc    = (const float*)d_in[23];
    const float* sc    = (const float*)d_in[24];
    const float* bc    = (const float*)d_in[25];
    const float* Wp    = (const float*)d_in[26];
    const float* sp    = (const float*)d_in[27];
    const float* bp    = (const float*)d_in[28];
    float* outp = (float*)d_out;

    prep_kernel<<<512, 256>>>(Wq, sq, bq, Wk, sk, bk, Wv, sv, bv,
                              wdw, sdw, bdw, Wpw, spw,
                              Wr, sr, Wc, sc, Wp, sp);

    gemm_kernel<0><<<dim3(512, 8), 256>>>(x, nullptr, nullptr, 256);

    mean_kernel<<<8192, 256>>>();
    attn_kernel<<<256, 64>>>(pe_rq, pe_rk, pe_cq, pe_ck);
    proj_kernel<<<2048, 256>>>(br, bc);

    gemm_kernel<1><<<dim3(512, 4), 256>>>(nullptr, bpw, nullptr, 512);
    gemm_kernel<2><<<dim3(512, 4), 256>>>(nullptr, bp, outp, 256);
}

// round 2
// speedup vs baseline: 1.7199x; 1.7199x over previous
#include <cuda_runtime.h>
#include <cstdint>

// ---------------------------------------------------------------------------
// ASE block: B=16, DIM=256, H=W=64, KEY_DIM=16, HEADS=8, NH_KD=128, DH=256
// N = B*H*W = 65536 spatial positions. All fp32.
//
// Pipeline:
//  1. prep      : fold BN scales into weight matrices
//  2. gemm<0>   : qkv0[512][N] = Wall @ x + ball
//  3. mean      : row/col means of qkv0 per (c,b)
//  4. attn      : axial attention (row + col)
//  5. proj      : relu + Wr/Wc projection
//  6. gemm<1>   : qkvg[256][N] = Wpw2 @ relu(qkv0*gs+gb) + bpw
//  7. gemm<2>   : out = hsig(Wp2 @ relu(v+xr+xc) + bp) * qkvg
//
// R1: GEMM rewritten as 128x128x8 double-buffered SGEMM, 8x8 register tile.
// ---------------------------------------------------------------------------

// ---- device scratch (no allocations allowed) ----
__device__ float g_Wall[512 * 256];
__device__ float g_ball[512];
__device__ float g_gs[512];
__device__ float g_gb[512];
__device__ float g_Wpw2[256 * 512];
__device__ float g_Wr2[256 * 256];
__device__ float g_Wc2[256 * 256];
__device__ float g_Wp2[256 * 256];
__device__ float g_qkv0[(size_t)512 * 65536];   // 128 MB
__device__ float g_qkvg[(size_t)256 * 65536];   //  64 MB
__device__ float g_rmean[512 * 16 * 64];
__device__ float g_cmean[512 * 16 * 64];
__device__ float g_attnpre[2 * 16 * 256 * 64];
__device__ float g_attnout[2 * 16 * 256 * 64];

// ---------------------------------------------------------------------------
// 1. weight prep
// ---------------------------------------------------------------------------
__global__ void prep_kernel(
    const float* __restrict__ Wq, const float* __restrict__ sq, const float* __restrict__ bq,
    const float* __restrict__ Wk, const float* __restrict__ sk, const float* __restrict__ bk,
    const float* __restrict__ Wv, const float* __restrict__ sv, const float* __restrict__ bv,
    const float* __restrict__ wdw, const float* __restrict__ sdw, const float* __restrict__ bdw,
    const float* __restrict__ Wpw, const float* __restrict__ spw,
    const float* __restrict__ Wr,  const float* __restrict__ sr,
    const float* __restrict__ Wc,  const float* __restrict__ sc,
    const float* __restrict__ Wp,  const float* __restrict__ sp)
{
    int i = blockIdx.x * 256 + threadIdx.x;     // 131072 threads
    {
        int m = i >> 8, c = i & 255;
        float w, s;
        if (m < 128)      { w = Wq[m * 256 + c];         s = sq[m]; }
        else if (m < 256) { w = Wk[(m - 128) * 256 + c]; s = sk[m - 128]; }
        else              { w = Wv[(m - 256) * 256 + c]; s = sv[m - 256]; }
        g_Wall[i] = w * s;
    }
    {
        int m = i >> 9;
        g_Wpw2[i] = Wpw[i] * spw[m];
    }
    if (i < 65536) {
        int m = i >> 8;
        g_Wr2[i] = Wr[i] * sr[m];
        g_Wc2[i] = Wc[i] * sc[m];
        g_Wp2[i] = Wp[i] * sp[m];
    }
    if (i < 512) {
        g_gs[i] = wdw[i] * sdw[i];
        g_gb[i] = bdw[i];
        float b;
        if (i < 128)      b = bq[i];
        else if (i < 256) b = bk[i - 128];
        else              b = bv[i - 256];
        g_ball[i] = b;
    }
}

// ---------------------------------------------------------------------------
// Tiled GEMM: BM=128, BN=128, BK=8, 256 threads, 8x8 per thread,
// double-buffered smem, one __syncthreads per K-step.
// ---------------------------------------------------------------------------
template <int MODE>
__global__ void __launch_bounds__(256) gemm_kernel(
    const float* __restrict__ xin,     // MODE 0 input x
    const float* __restrict__ biasM,   // MODE 1: bpw, MODE 2: bp
    float* __restrict__ outp,          // MODE 2: d_out
    int K)
{
    __shared__ float As[2][8][132];    // padded to dodge transpose-store conflicts
    __shared__ float Bs[2][8][128];

    const int tid = threadIdx.x;
    const int bm  = blockIdx.y * 128;
    const int bn0 = blockIdx.x * 128;
    const int tx  = tid & 15;          // N direction
    const int ty  = tid >> 4;          // M direction

    const float* __restrict__ Aw =
        (MODE == 0) ? g_Wall : ((MODE == 1) ? g_Wpw2 : g_Wp2);

    // A-tile loader mapping: 128 rows x 8 k, one float4 per thread
    const int arow = tid >> 1;
    const int akq  = (tid & 1) * 4;
    // B-tile loader mapping: 8 k x 128 n, one float4 per thread
    const int bkk  = tid >> 5;
    const int bnq  = (tid & 31) * 4;
    const int n    = bn0 + bnq;
    const int nb   = n >> 12;
    const int nhw  = n & 4095;
    const int nh   = nhw >> 6;
    const int nw   = nhw & 63;

    float acc[8][8];
    #pragma unroll
    for (int i = 0; i < 8; i++)
        #pragma unroll
        for (int j = 0; j < 8; j++) acc[i][j] = 0.0f;

    float4 pa, pb;

    auto loadG = [&](int k0) {
        pa = *(const float4*)&Aw[(size_t)(bm + arow) * K + k0 + akq];
        int k = k0 + bkk;
        if (MODE == 0) {
            pb = *(const float4*)&xin[(size_t)nb * 1048576 + (size_t)k * 4096 + nhw];
        } else if (MODE == 1) {
            float4 v = *(const float4*)&g_qkv0[(size_t)k * 65536 + n];
            float s = g_gs[k], b = g_gb[k];
            pb.x = fmaxf(v.x * s + b, 0.0f);
            pb.y = fmaxf(v.y * s + b, 0.0f);
            pb.z = fmaxf(v.z * s + b, 0.0f);
            pb.w = fmaxf(v.w * s + b, 0.0f);
        } else {
            float4 v = *(const float4*)&g_qkv0[(size_t)(256 + k) * 65536 + n];
            float xr = g_attnout[(size_t)(nb * 256 + k) * 64 + nh];
            const float* xcp = &g_attnout[(size_t)((16 + nb) * 256 + k) * 64 + nw];
            pb.x = fmaxf(v.x + xr + xcp[0], 0.0f);
            pb.y = fmaxf(v.y + xr + xcp[1], 0.0f);
            pb.z = fmaxf(v.z + xr + xcp[2], 0.0f);
            pb.w = fmaxf(v.w + xr + xcp[3], 0.0f);
        }
    };

    auto storeS = [&](int buf) {
        As[buf][akq + 0][arow] = pa.x;
        As[buf][akq + 1][arow] = pa.y;
        As[buf][akq + 2][arow] = pa.z;
        As[buf][akq + 3][arow] = pa.w;
        *(float4*)&Bs[buf][bkk][bnq] = pb;
    };

    auto compute = [&](int buf) {
        #pragma unroll
        for (int kk = 0; kk < 8; kk++) {
            float4 a0 = *(const float4*)&As[buf][kk][ty * 8];
            float4 a1 = *(const float4*)&As[buf][kk][ty * 8 + 4];
            float4 b0 = *(const float4*)&Bs[buf][kk][tx * 8];
            float4 b1 = *(const float4*)&Bs[buf][kk][tx * 8 + 4];
            float a[8] = {a0.x, a0.y, a0.z, a0.w, a1.x, a1.y, a1.z, a1.w};
            float b[8] = {b0.x, b0.y, b0.z, b0.w, b1.x, b1.y, b1.z, b1.w};
            #pragma unroll
            for (int i = 0; i < 8; i++)
                #pragma unroll
                for (int j = 0; j < 8; j++)
                    acc[i][j] += a[i] * b[j];
        }
    };

    loadG(0);
    storeS(0);
    __syncthreads();
    int buf = 0;
    for (int k0 = 8; k0 < K; k0 += 8) {
        loadG(k0);
        compute(buf);
        storeS(buf ^ 1);
        __syncthreads();
        buf ^= 1;
    }
    compute(buf);

    // epilogue: 8 rows x 2 float4 per thread
    #pragma unroll
    for (int i = 0; i < 8; i++) {
        int m = bm + ty * 8 + i;
        float bias = (MODE == 0) ? g_ball[m] : biasM[m];
        #pragma unroll
        for (int jq = 0; jq < 2; jq++) {
            int nn = bn0 + tx * 8 + jq * 4;
            float4 r;
            r.x = acc[i][jq * 4 + 0] + bias;
            r.y = acc[i][jq * 4 + 1] + bias;
            r.z = acc[i][jq * 4 + 2] + bias;
            r.w = acc[i][jq * 4 + 3] + bias;
            if (MODE == 0) {
                *(float4*)&g_qkv0[(size_t)m * 65536 + nn] = r;
            } else if (MODE == 1) {
                *(float4*)&g_qkvg[(size_t)m * 65536 + nn] = r;
            } else {
                float4 g = *(const float4*)&g_qkvg[(size_t)m * 65536 + nn];
                int b = nn >> 12, hw = nn & 4095;
                float4 o;
                o.x = fminf(fmaxf(r.x + 3.0f, 0.0f), 6.0f) * (1.0f / 6.0f) * g.x;
                o.y = fminf(fmaxf(r.y + 3.0f, 0.0f), 6.0f) * (1.0f / 6.0f) * g.y;
                o.z = fminf(fmaxf(r.z + 3.0f, 0.0f), 6.0f) * (1.0f / 6.0f) * g.z;
                o.w = fminf(fmaxf(r.w + 3.0f, 0.0f), 6.0f) * (1.0f / 6.0f) * g.w;
                *(float4*)&outp[(size_t)b * 1048576 + (size_t)m * 4096 + hw] = o;
            }
        }
    }
}

// ---------------------------------------------------------------------------
// 3. row/col means
// ---------------------------------------------------------------------------
__global__ void mean_kernel()
{
    __shared__ float sm[64][65];
    int bx = blockIdx.x;              // 8192 = 512 * 16
    int c = bx >> 4, b = bx & 15;
    const float* __restrict__ src = &g_qkv0[(size_t)c * 65536 + (size_t)b * 4096];
    int tid = threadIdx.x;            // 256
    for (int idx = tid; idx < 4096; idx += 256)
        sm[idx >> 6][idx & 63] = src[idx];
    __syncthreads();
    if (tid < 64) {
        float s = 0.0f;
        #pragma unroll
        for (int w = 0; w < 64; w++) s += sm[tid][w];
        g_rmean[(size_t)c * 1024 + b * 64 + tid] = s * (1.0f / 64.0f);
    } else if (tid < 128) {
        int w = tid - 64;
        float s = 0.0f;
        #pragma unroll
        for (int h = 0; h < 64; h++) s += sm[h][w];
        g_cmean[(size_t)c * 1024 + b * 64 + w] = s * (1.0f / 64.0f);
    }
}

// ---------------------------------------------------------------------------
// 4. axial attention
// ---------------------------------------------------------------------------
__global__ void attn_kernel(
    const float* __restrict__ pe_rq, const float* __restrict__ pe_rk,
    const float* __restrict__ pe_cq, const float* __restrict__ pe_ck)
{
    __shared__ float sQ[64][17];
    __shared__ float sK[64][17];
    __shared__ float sV[64][33];
    __shared__ float sS[64][65];
    int bx = blockIdx.x;              // 256 = 2 * 16 * 8
    int rc   = bx >> 7;
    int b    = (bx >> 3) & 15;
    int head = bx & 7;
    int i = threadIdx.x;              // 64 threads

    const float* __restrict__ mean = rc ? g_cmean : g_rmean;
    const float* __restrict__ peq  = rc ? pe_cq : pe_rq;
    const float* __restrict__ pek  = rc ? pe_ck : pe_rk;

    float pos = fminf(fmaxf(0.25f * (float)i - 0.25f, 0.0f), 15.0f);
    int   i0  = (int)pos;
    int   i1  = min(i0 + 1, 15);
    float fw  = pos - (float)i0;

    #pragma unroll
    for (int kd = 0; kd < 16; kd++) {
        int cq = head * 16 + kd;
        float pq = peq[cq * 16 + i0] * (1.0f - fw) + peq[cq * 16 + i1] * fw;
        float pk = pek[cq * 16 + i0] * (1.0f - fw) + pek[cq * 16 + i1] * fw;
        sQ[i][kd] = mean[(size_t)cq * 1024 + b * 64 + i] + pq;
        sK[i][kd] = mean[(size_t)(128 + cq) * 1024 + b * 64 + i] + pk;
    }
    #pragma unroll
    for (int d = 0; d < 32; d++) {
        int cv = 256 + head * 32 + d;
        sV[i][d] = mean[(size_t)cv * 1024 + b * 64 + i];
    }
    __syncthreads();

    float mx = -1e30f;
    for (int j = 0; j < 64; j++) {
        float s = 0.0f;
        #pragma unroll
        for (int kd = 0; kd < 16; kd++) s += sQ[i][kd] * sK[j][kd];
        s *= 0.25f;
        sS[i][j] = s;
        mx = fmaxf(mx, s);
    }
    float sum = 0.0f;
    for (int j = 0; j < 64; j++) {
        float e = expf(sS[i][j] - mx);
        sS[i][j] = e;
        sum += e;
    }
    float inv = 1.0f / sum;
    #pragma unroll 4
    for (int d = 0; d < 32; d++) {
        float o = 0.0f;
        for (int j = 0; j < 64; j++) o += sS[i][j] * sV[j][d];
        g_attnpre[(size_t)((rc * 16 + b) * 256 + head * 32 + d) * 64 + i] = o * inv;
    }
}

// ---------------------------------------------------------------------------
// 5. relu + Wr/Wc projection
// ---------------------------------------------------------------------------
__global__ void proj_kernel(const float* __restrict__ br, const float* __restrict__ bc)
{
    int bx = blockIdx.x;              // 2048 = 2 * 16 * 64
    int rc = bx & 1;
    int b  = (bx >> 1) & 15;
    int ob = bx >> 5;
    int tid = threadIdx.x;            // 256
    int h = tid & 63;
    int o = ob * 4 + (tid >> 6);

    const float* __restrict__ W    = rc ? g_Wc2 : g_Wr2;
    const float* __restrict__ bias = rc ? bc : br;
    const float* __restrict__ in   = &g_attnpre[(size_t)(rc * 16 + b) * 256 * 64];

    float acc = bias[o];
    #pragma unroll 8
    for (int k = 0; k < 256; k++)
        acc += W[o * 256 + k] * fmaxf(in[k * 64 + h], 0.0f);

    g_attnout[(size_t)((rc * 16 + b) * 256 + o) * 64 + h] = acc;
}

// ---------------------------------------------------------------------------
extern "C" void kernel_launch(void* const* d_in, const int* in_sizes, int n_in,
                              void* d_out, int out_size)
{
    (void)in_sizes; (void)n_in; (void)out_size;
    const float* x     = (const float*)d_in[0];
    const float* Wq    = (const float*)d_in[1];
    const float* sq    = (const float*)d_in[2];
    const float* bq    = (const float*)d_in[3];
    const float* Wk    = (const float*)d_in[4];
    const float* sk    = (const float*)d_in[5];
    const float* bk    = (const float*)d_in[6];
    const float* Wv    = (const float*)d_in[7];
    const float* sv    = (const float*)d_in[8];
    const float* bv    = (const float*)d_in[9];
    const float* pe_rq = (const float*)d_in[10];
    const float* pe_rk = (const float*)d_in[11];
    const float* pe_cq = (const float*)d_in[12];
    const float* pe_ck = (const float*)d_in[13];
    const float* wdw   = (const float*)d_in[14];
    const float* sdw   = (const float*)d_in[15];
    const float* bdw   = (const float*)d_in[16];
    const float* Wpw   = (const float*)d_in[17];
    const float* spw   = (const float*)d_in[18];
    const float* bpw   = (const float*)d_in[19];
    const float* Wr    = (const float*)d_in[20];
    const float* sr    = (const float*)d_in[21];
    const float* br    = (const float*)d_in[22];
    const float* Wc    = (const float*)d_in[23];
    const float* sc    = (const float*)d_in[24];
    const float* bc    = (const float*)d_in[25];
    const float* Wp    = (const float*)d_in[26];
    const float* sp    = (const float*)d_in[27];
    const float* bp    = (const float*)d_in[28];
    float* outp = (float*)d_out;

    prep_kernel<<<512, 256>>>(Wq, sq, bq, Wk, sk, bk, Wv, sv, bv,
                              wdw, sdw, bdw, Wpw, spw,
                              Wr, sr, Wc, sc, Wp, sp);

    gemm_kernel<0><<<dim3(512, 4), 256>>>(x, nullptr, nullptr, 256);

    mean_kernel<<<8192, 256>>>();
    attn_kernel<<<256, 64>>>(pe_rq, pe_rk, pe_cq, pe_ck);
    proj_kernel<<<2048, 256>>>(br, bc);

    gemm_kernel<1><<<dim3(512, 2), 256>>>(nullptr, bpw, nullptr, 512);
    gemm_kernel<2><<<dim3(512, 2), 256>>>(nullptr, bp, outp, 256);
}